// round 13
// baseline (speedup 1.0000x reference)
#include <cuda_runtime.h>
#include <cuda_bf16.h>
#include <math.h>
#include <stdint.h>

#define B 64
#define NP 32
#define NS 72
#define HD 256
#define H 4
#define F 64
#define CSE 112
#define L 4
#define NC 110
#define EPS 1e-6f
#define NBLK 148

// ---------------- device scratch (no allocations; device-code refs only) ----------------
__device__ float g_c [L*B*HD];
__device__ float g_x [B*NS*HD];
__device__ float g_hl[B*NS*HD];
__device__ float g_hr[B*NS*HD];
__device__ __nv_bfloat16 g_Ghi[B*NS*HD];
__device__ __nv_bfloat16 g_Glo[B*NS*HD];
__device__ __nv_bfloat16 g_Bhi[L*768*HD];
__device__ __nv_bfloat16 g_Blo[L*768*HD];
__device__ unsigned g_barcnt;
__device__ unsigned g_bargen;

#define SWZ128(bo) ((bo) ^ (((bo) >> 3) & 0x70))

__device__ __forceinline__ uint32_t smem_u32(const void* p) {
    uint32_t a;
    asm("{ .reg .u64 t; cvta.to.shared.u64 t, %1; cvt.u32.u64 %0, t; }" : "=r"(a) : "l"(p));
    return a;
}
#define LDM_X4(r0, r1, r2, r3, addr) \
    asm volatile("ldmatrix.sync.aligned.m8n8.x4.shared.b16 {%0,%1,%2,%3}, [%4];" \
                 : "=r"(r0), "=r"(r1), "=r"(r2), "=r"(r3) : "r"(addr))
#define CPA16(dst, src) \
    asm volatile("cp.async.cg.shared.global [%0], [%1], 16;" :: "r"(dst), "l"(src))
#define CPA_COMMIT() asm volatile("cp.async.commit_group;" ::: "memory")

__device__ __forceinline__ void mma_bf16(float* c, const uint32_t* a, const uint32_t* b) {
    asm volatile(
        "mma.sync.aligned.m16n8k16.row.col.f32.bf16.bf16.f32 "
        "{%0,%1,%2,%3}, {%4,%5,%6,%7}, {%8,%9}, {%0,%1,%2,%3};"
        : "+f"(c[0]), "+f"(c[1]), "+f"(c[2]), "+f"(c[3])
        : "r"(a[0]), "r"(a[1]), "r"(a[2]), "r"(a[3]), "r"(b[0]), "r"(b[1]));
}
__device__ __forceinline__ uint32_t bf2u(__nv_bfloat162 v) { return *(uint32_t*)&v; }

// ---------------- generational grid barrier (all 148 CTAs co-resident) ----------------
__device__ __forceinline__ void gbar() {
    __syncthreads();
    __threadfence();                       // release: writes -> L2, L1 invalidate
    __syncthreads();
    if (threadIdx.x == 0) {
        volatile unsigned* vg = &g_bargen;
        unsigned g = *vg;
        unsigned prev = atomicAdd(&g_barcnt, 1u);
        if (prev == NBLK - 1u) {
            g_barcnt = 0u;
            __threadfence();
            atomicAdd(&g_bargen, 1u);
        } else {
            while (*vg == g) __nanosleep(128);
        }
    }
    __syncthreads();
    __threadfence();                       // acquire: invalidate L1 before fresh reads
}

// ---------------- block LN statistics over 256 threads ----------------
__device__ __forceinline__ void block_stats256(float val, float& mean, float& rstd) {
    float s = val, sq = val * val;
    #pragma unroll
    for (int o = 16; o; o >>= 1) {
        s  += __shfl_xor_sync(0xffffffffu, s,  o);
        sq += __shfl_xor_sync(0xffffffffu, sq, o);
    }
    __shared__ float ss[8], sqq[8];
    int lane = threadIdx.x & 31, w = threadIdx.x >> 5;
    if (lane == 0) { ss[w] = s; sqq[w] = sq; }
    __syncthreads();
    if (w == 0) {
        s  = (lane < 8) ? ss[lane]  : 0.f;
        sq = (lane < 8) ? sqq[lane] : 0.f;
        #pragma unroll
        for (int o = 4; o; o >>= 1) {
            s  += __shfl_xor_sync(0xffffffffu, s,  o);
            sq += __shfl_xor_sync(0xffffffffu, sq, o);
        }
        if (lane == 0) { ss[0] = s; sqq[0] = sq; }
    }
    __syncthreads();
    s = ss[0]; sq = sqq[0];
    mean = s * (1.f / 256.f);
    float var = sq * (1.f / 256.f) - mean * mean;
    rstd = rsqrtf(var + EPS);
}

// ================= tile bodies (smc = dynamic smem base) =================

__device__ void embed_tile(char* smc, int b, const float* __restrict__ so,
                           const float* __restrict__ in_W, const float* __restrict__ in_b) {
    __syncthreads();
    float* sv = (float*)smc;               // [NP][NS]
    int d = threadIdx.x;
    float w[NP];
    #pragma unroll
    for (int p = 0; p < NP; p++) w[p] = in_W[p*HD + d];
    for (int k = d; k < NP*NS; k += 256) sv[k] = so[b*NP*NS + k];
    __syncthreads();
    float bb = in_b[d];
    for (int s = 0; s < NS; s++) {
        float acc = bb;
        #pragma unroll
        for (int p = 0; p < NP; p++) acc = fmaf(sv[p*NS + s], w[p], acc);
        g_x[(size_t)(b*NS + s)*HD + d] = acc;
    }
}

__device__ void convW_tile(char* smc, int idx, const float* __restrict__ Wl,
                           const float* __restrict__ Wr, const float* __restrict__ Wo) {
    __syncthreads();
    float (*t)[33] = (float(*)[33])smc;
    int kt = idx & 7, nt = (idx >> 3) & 7, m = idx >> 6;
    int l = m / 3, sel = m - l*3;
    const float* src = (sel == 0 ? Wl : sel == 1 ? Wr : Wo) + (size_t)l*HD*HD;
    int k0 = kt*32, n0 = nt*32;
    int x = threadIdx.x & 31, y = threadIdx.x >> 5;
    #pragma unroll
    for (int yy = y; yy < 32; yy += 8)
        t[yy][x] = src[(size_t)(k0 + yy)*HD + n0 + x];
    __syncthreads();
    int drow0 = l*768 + sel*256 + n0;
    #pragma unroll
    for (int yy = y; yy < 32; yy += 8) {
        float v = t[x][yy];
        __nv_bfloat16 hh = __float2bfloat16(v);
        size_t di = (size_t)(drow0 + yy)*HD + k0 + x;
        g_Bhi[di] = hh;
        g_Blo[di] = __float2bfloat16(v - __bfloat162float(hh));
    }
}

__device__ void cp_tile(char* smc, int idx, const float* __restrict__ cc,
                        const float* __restrict__ ctx_W, const float* __restrict__ ctx_b,
                        const float* __restrict__ lnc_s, const float* __restrict__ lnc_b,
                        const float* __restrict__ cp_W, const float* __restrict__ cp_b) {
    __syncthreads();
    float* cs = (float*)smc;               // CSE
    float* gs = (float*)(smc + 512);       // HD
    int b = idx & 63, l = idx >> 6;
    int tid = threadIdx.x;
    if (tid < CSE) cs[tid] = cc[b*CSE + tid];
    __syncthreads();
    float acc = ctx_b[tid];
    #pragma unroll 4
    for (int k = 0; k < CSE; k++) acc += cs[k] * ctx_W[k*HD + tid];
    float mean, rstd;
    block_stats256(acc, mean, rstd);
    gs[tid] = fmaxf((acc - mean)*rstd*lnc_s[tid] + lnc_b[tid], 0.f);
    __syncthreads();
    const float* W = cp_W + (size_t)l*HD*HD;
    float a2 = cp_b[l*HD + tid];
    #pragma unroll 16
    for (int k = 0; k < HD; k++) a2 += gs[k] * W[k*HD + tid];
    g_c[(l*B + b)*HD + tid] = a2;
}

// gemm0 with fused LN: tile tt in [0,288): bx = tt%36, by = tt/36
#define G0_AH 0
#define G0_AL 16384
#define G0_BH 32768
#define G0_BL 40960
#define G0_ST 49152
__device__ void gemm0_tile(char* smc, int tt, int l, const float* __restrict__ lns,
                           const float* __restrict__ lnb) {
    __syncthreads();
    uint32_t sbase = smem_u32(smc);
    float* stats = (float*)(smc + G0_ST);
    int tid = threadIdx.x, lane = tid & 31, warp = tid >> 5;
    int wm = warp >> 1, wn = warp & 1;
    int m0 = (tt % 36) * 128, nloc = (tt / 36) * 64;
    const __nv_bfloat16* Bhi = g_Bhi + (size_t)(l*768 + nloc) * HD;
    const __nv_bfloat16* Blo = g_Blo + (size_t)(l*768 + nloc) * HD;

    int row = tid >> 1, half = tid & 1;
    {
        const float4* xr = (const float4*)(g_x + (size_t)(m0 + row)*HD + half*128);
        float s = 0.f, sq = 0.f;
        #pragma unroll
        for (int c = 0; c < 32; c++) {
            float4 v = xr[c];
            s  += v.x + v.y + v.z + v.w;
            sq += v.x*v.x + v.y*v.y + v.z*v.z + v.w*v.w;
        }
        s  += __shfl_xor_sync(0xffffffffu, s, 1);
        sq += __shfl_xor_sync(0xffffffffu, sq, 1);
        if (half == 0) {
            float mean = s * (1.f/256.f);
            float var  = sq * (1.f/256.f) - mean*mean;
            stats[row*2]     = mean;
            stats[row*2 + 1] = rsqrtf(var + EPS);
        }
    }
    __syncthreads();

    int bidx = (m0 + row) / NS;
    const float* crow = g_c + (size_t)(l*B + bidx)*HD;
    int brow = tid >> 2, bq = tid & 3;
    int sub = lane >> 3, lrow = lane & 7;
    int lr = lane >> 2, lc2 = (lane & 3) * 2;

    float acc[2][4][4];
    #pragma unroll
    for (int mt = 0; mt < 2; mt++)
        #pragma unroll
        for (int nt = 0; nt < 4; nt++)
            #pragma unroll
            for (int c = 0; c < 4; c++) acc[mt][nt][c] = 0.f;

    for (int kc = 0; kc < 4; kc++) {
        if (kc) __syncthreads();
        {
            float mean = stats[row*2], rstd = stats[row*2 + 1];
            int colbase = kc*64 + half*32;
            const float4* src = (const float4*)(g_x + (size_t)(m0 + row)*HD + colbase);
            const float4* ls4 = (const float4*)(lns + colbase);
            const float4* lb4 = (const float4*)(lnb + colbase);
            const float4* cr4 = (const float4*)(crow + colbase);
            #pragma unroll
            for (int c = 0; c < 8; c++) {
                float4 v = src[c], sg = ls4[c], bt = lb4[c], cv = cr4[c];
                float y0 = (v.x - mean)*rstd*sg.x + bt.x + cv.x;
                float y1 = (v.y - mean)*rstd*sg.y + bt.y + cv.y;
                float y2 = (v.z - mean)*rstd*sg.z + bt.z + cv.z;
                float y3 = (v.w - mean)*rstd*sg.w + bt.w + cv.w;
                __nv_bfloat162 h01 = __floats2bfloat162_rn(y0, y1);
                __nv_bfloat162 h23 = __floats2bfloat162_rn(y2, y3);
                __nv_bfloat162 l01 = __floats2bfloat162_rn(y0 - __bfloat162float(h01.x),
                                                           y1 - __bfloat162float(h01.y));
                __nv_bfloat162 l23 = __floats2bfloat162_rn(y2 - __bfloat162float(h23.x),
                                                           y3 - __bfloat162float(h23.y));
                uint32_t sw = SWZ128((uint32_t)(row*128 + half*64 + c*8));
                *(uint2*)(smc + G0_AH + sw) = make_uint2(bf2u(h01), bf2u(h23));
                *(uint2*)(smc + G0_AL + sw) = make_uint2(bf2u(l01), bf2u(l23));
            }
        }
        {
            const uint4* bh4 = (const uint4*)((const char*)(Bhi + (size_t)brow*HD + kc*64) + bq*32);
            const uint4* bl4 = (const uint4*)((const char*)(Blo + (size_t)brow*HD + kc*64) + bq*32);
            #pragma unroll
            for (int c = 0; c < 2; c++) {
                uint32_t sw = SWZ128((uint32_t)(brow*128 + bq*32 + c*16));
                *(uint4*)(smc + G0_BH + sw) = bh4[c];
                *(uint4*)(smc + G0_BL + sw) = bl4[c];
            }
        }
        __syncthreads();
        #pragma unroll
        for (int ks = 0; ks < 4; ks++) {
            uint32_t ah[2][4], al[2][4], bh[4][2], bl[4][2];
            #pragma unroll
            for (int mt = 0; mt < 2; mt++) {
                int ar = wm*32 + mt*16 + (sub & 1)*8 + lrow;
                int ac = ks*32 + (sub >> 1)*16;
                uint32_t off = SWZ128((uint32_t)(ar*128 + ac));
                LDM_X4(ah[mt][0], ah[mt][1], ah[mt][2], ah[mt][3], sbase + G0_AH + off);
                LDM_X4(al[mt][0], al[mt][1], al[mt][2], al[mt][3], sbase + G0_AL + off);
            }
            #pragma unroll
            for (int pair = 0; pair < 2; pair++) {
                int ntb = sub >> 1, khalf = sub & 1;
                int br = wn*32 + pair*16 + ntb*8 + lrow;
                int bc = ks*32 + khalf*16;
                uint32_t off = SWZ128((uint32_t)(br*128 + bc));
                LDM_X4(bh[2*pair][0], bh[2*pair][1], bh[2*pair+1][0], bh[2*pair+1][1],
                       sbase + G0_BH + off);
                LDM_X4(bl[2*pair][0], bl[2*pair][1], bl[2*pair+1][0], bl[2*pair+1][1],
                       sbase + G0_BL + off);
            }
            #pragma unroll
            for (int mt = 0; mt < 2; mt++)
                #pragma unroll
                for (int nt = 0; nt < 4; nt++) {
                    mma_bf16(acc[mt][nt], ah[mt], bh[nt]);
                    mma_bf16(acc[mt][nt], ah[mt], bl[nt]);
                    mma_bf16(acc[mt][nt], al[mt], bh[nt]);
                }
        }
    }

    #pragma unroll
    for (int mt = 0; mt < 2; mt++) {
        int r = m0 + wm*32 + mt*16 + lr;
        #pragma unroll
        for (int nt = 0; nt < 4; nt++) {
            int gn = nloc + wn*32 + nt*8 + lc2;
            float* C = (gn < 256) ? g_hl : g_hr;
            int cc2 = gn & 255;
            C[(size_t)r*HD + cc2]         = acc[mt][nt][0];
            C[(size_t)r*HD + cc2 + 1]     = acc[mt][nt][1];
            C[(size_t)(r+8)*HD + cc2]     = acc[mt][nt][2];
            C[(size_t)(r+8)*HD + cc2 + 1] = acc[mt][nt][3];
        }
    }
}

// gemm1: tile tt in [0,144): bx = tt%36, by = tt/36; cp.async double buffer
#define GSTAGE 49152
__device__ void gemm1_tile(char* smc, int tt, int wrow, const float* __restrict__ bias) {
    __syncthreads();
    uint32_t sbase = smem_u32(smc);
    int tid = threadIdx.x, lane = tid & 31, warp = tid >> 5;
    int wm = warp >> 1, wn = warp & 1;
    int m0   = (tt % 36) * 128;
    int nloc = (tt / 36) * 64;
    const __nv_bfloat16* Bhi = g_Bhi + (size_t)(wrow + nloc) * HD;
    const __nv_bfloat16* Blo = g_Blo + (size_t)(wrow + nloc) * HD;
    int lr = lane >> 2, lc2 = (lane & 3) * 2;
    int arow = tid >> 1, ahalf = tid & 1;
    int brow = tid >> 2, bq = tid & 3;

    auto load_stage = [&](int kc, int buf) {
        uint32_t sb = sbase + buf * GSTAGE;
        const char* gAh = (const char*)(g_Ghi + (size_t)(m0 + arow)*HD + kc*64) + ahalf*64;
        const char* gAl = (const char*)(g_Glo + (size_t)(m0 + arow)*HD + kc*64) + ahalf*64;
        #pragma unroll
        for (int c = 0; c < 4; c++) {
            uint32_t sw = SWZ128((uint32_t)(arow*128 + ahalf*64 + c*16));
            CPA16(sb + sw, gAh + c*16);
            CPA16(sb + 16384 + sw, gAl + c*16);
        }
        const char* gBh = (const char*)(Bhi + (size_t)brow*HD + kc*64) + bq*32;
        const char* gBl = (const char*)(Blo + (size_t)brow*HD + kc*64) + bq*32;
        #pragma unroll
        for (int c = 0; c < 2; c++) {
            uint32_t sw = SWZ128((uint32_t)(brow*128 + bq*32 + c*16));
            CPA16(sb + 32768 + sw, gBh + c*16);
            CPA16(sb + 40960 + sw, gBl + c*16);
        }
        CPA_COMMIT();
    };

    float acc[2][4][4];
    #pragma unroll
    for (int mt = 0; mt < 2; mt++)
        #pragma unroll
        for (int nt = 0; nt < 4; nt++)
            #pragma unroll
            for (int c = 0; c < 4; c++) acc[mt][nt][c] = 0.f;

    load_stage(0, 0);
    load_stage(1, 1);
    int sub = lane >> 3, lrow = lane & 7;

    for (int kc = 0; kc < 4; kc++) {
        if (kc == 3) asm volatile("cp.async.wait_group 0;" ::: "memory");
        else         asm volatile("cp.async.wait_group 1;" ::: "memory");
        __syncthreads();
        uint32_t sb = sbase + (kc & 1) * GSTAGE;
        #pragma unroll
        for (int ks = 0; ks < 4; ks++) {
            uint32_t ah[2][4], al[2][4], bh[4][2], bl[4][2];
            #pragma unroll
            for (int mt = 0; mt < 2; mt++) {
                int ar = wm*32 + mt*16 + (sub & 1)*8 + lrow;
                int ac = ks*32 + (sub >> 1)*16;
                uint32_t off = SWZ128((uint32_t)(ar*128 + ac));
                LDM_X4(ah[mt][0], ah[mt][1], ah[mt][2], ah[mt][3], sb + off);
                LDM_X4(al[mt][0], al[mt][1], al[mt][2], al[mt][3], sb + 16384 + off);
            }
            #pragma unroll
            for (int pair = 0; pair < 2; pair++) {
                int ntb = sub >> 1, khalf = sub & 1;
                int br = wn*32 + pair*16 + ntb*8 + lrow;
                int bc = ks*32 + khalf*16;
                uint32_t off = SWZ128((uint32_t)(br*128 + bc));
                LDM_X4(bh[2*pair][0], bh[2*pair][1], bh[2*pair+1][0], bh[2*pair+1][1],
                       sb + 32768 + off);
                LDM_X4(bl[2*pair][0], bl[2*pair][1], bl[2*pair+1][0], bl[2*pair+1][1],
                       sb + 40960 + off);
            }
            #pragma unroll
            for (int mt = 0; mt < 2; mt++)
                #pragma unroll
                for (int nt = 0; nt < 4; nt++) {
                    mma_bf16(acc[mt][nt], ah[mt], bh[nt]);
                    mma_bf16(acc[mt][nt], ah[mt], bl[nt]);
                    mma_bf16(acc[mt][nt], al[mt], bh[nt]);
                }
        }
        __syncthreads();
        if (kc < 2) load_stage(kc + 2, kc & 1);
    }

    #pragma unroll
    for (int mt = 0; mt < 2; mt++) {
        int r = m0 + wm*32 + mt*16 + lr;
        #pragma unroll
        for (int nt = 0; nt < 4; nt++) {
            int gn = nloc + wn*32 + nt*8 + lc2;
            g_x[(size_t)r*HD + gn]         += acc[mt][nt][0] + bias[gn];
            g_x[(size_t)r*HD + gn + 1]     += acc[mt][nt][1] + bias[gn + 1];
            g_x[(size_t)(r+8)*HD + gn]     += acc[mt][nt][2] + bias[gn];
            g_x[(size_t)(r+8)*HD + gn + 1] += acc[mt][nt][3] + bias[gn + 1];
        }
    }
}

// attention: tile tt in [0,384): b = tt&63, chunk = tt>>6. TI=12
#define TI 12
#define A_HRS 0
#define A_HLS (NS*HD)
#define A_SC  (A_HLS + TI*HD)
#define A_ADJ (A_SC + TI*NS*H)
#define A_WA  (A_ADJ + TI*NS)
__device__ void attn_tile(char* smc, int tt, const float* __restrict__ adj,
                          const float* __restrict__ Wa) {
    __syncthreads();
    float* smf = (float*)smc;
    int b = tt & 63;
    int i0 = (tt >> 6) * TI;
    int tid = threadIdx.x, lane = tid & 31, warp = tid >> 5;
    float* hrs  = smf + A_HRS;
    float* hls  = smf + A_HLS;
    float* sc   = smf + A_SC;
    float* adjr = smf + A_ADJ;
    float* wa_s = smf + A_WA;
    wa_s[tid] = Wa[tid];
    {
        const float4* sr = (const float4*)(g_hr + (size_t)b*NS*HD);
        float4* dr = (float4*)hrs;
        for (int k = tid; k < NS*HD/4; k += 256) dr[k] = sr[k];
        const float4* sl = (const float4*)(g_hl + (size_t)(b*NS + i0)*HD);
        float4* dl = (float4*)hls;
        for (int k = tid; k < TI*HD/4; k += 256) dl[k] = sl[k];
        for (int k = tid; k < TI*NS; k += 256) adjr[k] = adj[(i0 + k/NS)*NS + (k % NS)];
    }
    __syncthreads();

    for (int e = tid; e < TI*NS*H; e += 256) {
        int i = e / (NS*H);
        int rem = e - i*(NS*H);
        int j = rem >> 2, h = rem & 3;
        float outv = -1e9f;
        if (adjr[i*NS + j] > 0.f) {
            const float* pl = hls + i*HD + h*F;
            const float* pr = hrs + j*HD + h*F;
            const float* pw = wa_s + h*F;
            float p = 0.f;
            int f = lane;
            #pragma unroll 8
            for (int ff = 0; ff < F; ff++) {
                float v = pl[f] + pr[f];
                v = (v > 0.f) ? v : 0.2f * v;
                p = fmaf(pw[f], v, p);
                f = (f + 1) & 63;
            }
            outv = p;
        }
        sc[(i*NS + j)*H + h] = outv;
    }
    __syncthreads();

    for (int p = warp; p < TI*H; p += 8) {
        int i = p >> 2, h = p & 3;
        float m = -1e30f;
        for (int j = lane; j < NS; j += 32) m = fmaxf(m, sc[(i*NS + j)*H + h]);
        #pragma unroll
        for (int o = 16; o; o >>= 1) m = fmaxf(m, __shfl_xor_sync(0xffffffffu, m, o));
        float s = 0.f;
        for (int j = lane; j < NS; j += 32) {
            float e2 = expf(sc[(i*NS + j)*H + h] - m);
            sc[(i*NS + j)*H + h] = e2; s += e2;
        }
        #pragma unroll
        for (int o = 16; o; o >>= 1) s += __shfl_xor_sync(0xffffffffu, s, o);
        float inv = 1.f / s;
        for (int j = lane; j < NS; j += 32) sc[(i*NS + j)*H + h] *= inv;
    }
    __syncthreads();

    int d = tid, h = d >> 6;
    float acc[TI] = {};
    for (int j = 0; j < NS; j++) {
        float hv = hrs[j*HD + d];
        #pragma unroll
        for (int i = 0; i < TI; i++) acc[i] += sc[(i*NS + j)*H + h] * hv;
    }
    #pragma unroll
    for (int i = 0; i < TI; i++) {
        float v = acc[i];
        __nv_bfloat16 hh = __float2bfloat16(v);
        size_t idx = (size_t)(b*NS + i0 + i)*HD + d;
        g_Ghi[idx] = hh;
        g_Glo[idx] = __float2bfloat16(v - __bfloat162float(hh));
    }
}

// heads: tile = batch b
#define OUT_CARD 0
#define OUT_AT   (B*NC)
#define OUT_SRC  (OUT_AT + B*3)
#define OUT_TGT  (OUT_SRC + B*NS)
#define OUT_VAL  (OUT_TGT + B*NS)
__device__ void heads_tile(char* smc, int b,
                           const float* __restrict__ cW, const float* __restrict__ cb,
                           const float* __restrict__ aW, const float* __restrict__ ab,
                           const float* __restrict__ sW, const float* __restrict__ sb,
                           const float* __restrict__ tW, const float* __restrict__ tb,
                           const float* __restrict__ v1W, const float* __restrict__ v1b,
                           const float* __restrict__ v2W, const float* __restrict__ v2b,
                           float* __restrict__ out) {
    __syncthreads();
    float* ge = (float*)smc;
    float* vh = ge + HD;
    float* vpart = vh + 128;
    int tid = threadIdx.x;
    {
        float m = 0.f;
        #pragma unroll 8
        for (int s = 0; s < NS; s++) m += g_x[(size_t)(b*NS + s)*HD + tid];
        ge[tid] = m * (1.f / (float)NS);
    }
    __syncthreads();
    if (tid < NC) {
        float a = cb[tid];
        for (int k = 0; k < HD; k++) a += ge[k] * cW[k*NC + tid];
        out[OUT_CARD + b*NC + tid] = a;
    }
    if (tid < 3) {
        float a = ab[tid];
        for (int k = 0; k < HD; k++) a += ge[k] * aW[k*3 + tid];
        out[OUT_AT + b*3 + tid] = a;
    }
    if (tid < NS) {
        float a = sb[tid], t = tb[tid];
        for (int k = 0; k < HD; k++) { a += ge[k] * sW[k*NS + tid]; t += ge[k] * tW[k*NS + tid]; }
        out[OUT_SRC + b*NS + tid] = a;
        out[OUT_TGT + b*NS + tid] = t;
    }
    if (tid < 128) {
        float a = v1b[tid];
        for (int k = 0; k < HD; k++) a += ge[k] * v1W[k*128 + tid];
        vh[tid] = fmaxf(a, 0.f);
    }
    __syncthreads();
    if (tid < 128) {
        float p = vh[tid] * v2W[tid];
        #pragma unroll
        for (int o = 16; o; o >>= 1) p += __shfl_xor_sync(0xffffffffu, p, o);
        if ((tid & 31) == 0) vpart[tid >> 5] = p;
    }
    __syncthreads();
    if (tid == 0) {
        float s = vpart[0] + vpart[1] + vpart[2] + vpart[3] + v2b[0];
        out[OUT_VAL + b] = tanhf(s);
    }
}

// ================= mega kernel =================
#define SMEM_TOTAL 104448
__global__ void __launch_bounds__(256) mega_kernel(
    const float* __restrict__ so, const float* __restrict__ cc, const float* __restrict__ adj,
    const float* __restrict__ ctx_W, const float* __restrict__ ctx_b,
    const float* __restrict__ lnc_s, const float* __restrict__ lnc_b,
    const float* __restrict__ in_W, const float* __restrict__ in_b,
    const float* __restrict__ lnp_s, const float* __restrict__ lnp_b,
    const float* __restrict__ cp_W, const float* __restrict__ cp_b,
    const float* __restrict__ Wl, const float* __restrict__ Wr,
    const float* __restrict__ Wa, const float* __restrict__ op_W,
    const float* __restrict__ op_b,
    const float* __restrict__ cW, const float* __restrict__ cb,
    const float* __restrict__ aW, const float* __restrict__ ab,
    const float* __restrict__ sW, const float* __restrict__ sbv,
    const float* __restrict__ tW, const float* __restrict__ tb,
    const float* __restrict__ v1W, const float* __restrict__ v1b,
    const float* __restrict__ v2W, const float* __restrict__ v2b,
    float* __restrict__ out) {
    extern __shared__ char smc[];
    int bid = blockIdx.x;

    // ---- prep phase: embed (64) | convW (768) | ctx+cp (256) ----
    for (int t = bid; t < 64 + 768 + 256; t += NBLK) {
        if (t < 64)            embed_tile(smc, t, so, in_W, in_b);
        else if (t < 64 + 768) convW_tile(smc, t - 64, Wl, Wr, op_W);
        else                   cp_tile(smc, t - (64 + 768), cc, ctx_W, ctx_b,
                                       lnc_s, lnc_b, cp_W, cp_b);
    }
    gbar();

    for (int l = 0; l < L; l++) {
        for (int t = bid; t < 288; t += NBLK)
            gemm0_tile(smc, t, l, lnp_s + l*HD, lnp_b + l*HD);
        gbar();
        for (int t = bid; t < 384; t += NBLK)
            attn_tile(smc, t, adj, Wa + l*H*F);
        gbar();
        for (int t = bid; t < 144; t += NBLK)
            gemm1_tile(smc, t, l*768 + 512, op_b + l*HD);
        gbar();
    }

    for (int t = bid; t < B; t += NBLK)
        heads_tile(smc, t, cW, cb, aW, ab, sW, sbv, tW, tb, v1W, v1b, v2W, v2b, out);
}

// ---------------- launch ----------------
extern "C" void kernel_launch(void* const* d_in, const int* in_sizes, int n_in,
                              void* d_out, int out_size) {
    const float* spatial_obs = (const float*)d_in[0];
    const float* card_ctx    = (const float*)d_in[1];
    const float* adj         = (const float*)d_in[2];
    const float* ctx_W  = (const float*)d_in[3];
    const float* ctx_b  = (const float*)d_in[4];
    const float* lnc_s  = (const float*)d_in[5];
    const float* lnc_b  = (const float*)d_in[6];
    const float* in_W   = (const float*)d_in[7];
    const float* in_b   = (const float*)d_in[8];
    const float* lnp_s  = (const float*)d_in[9];
    const float* lnp_b  = (const float*)d_in[10];
    const float* cp_W   = (const float*)d_in[11];
    const float* cp_b   = (const float*)d_in[12];
    const float* Wl     = (const float*)d_in[13];
    const float* Wr     = (const float*)d_in[14];
    const float* Wa     = (const float*)d_in[15];
    const float* op_W   = (const float*)d_in[16];
    const float* op_b   = (const float*)d_in[17];
    const float* card_W = (const float*)d_in[18];
    const float* card_b = (const float*)d_in[19];
    const float* at_W   = (const float*)d_in[20];
    const float* at_b   = (const float*)d_in[21];
    const float* src_W  = (const float*)d_in[22];
    const float* src_b  = (const float*)d_in[23];
    const float* tgt_W  = (const float*)d_in[24];
    const float* tgt_b  = (const float*)d_in[25];
    const float* v1_W   = (const float*)d_in[26];
    const float* v1_b   = (const float*)d_in[27];
    const float* v2_W   = (const float*)d_in[28];
    const float* v2_b   = (const float*)d_in[29];
    float* out = (float*)d_out;

    cudaFuncSetAttribute(mega_kernel, cudaFuncAttributeMaxDynamicSharedMemorySize, SMEM_TOTAL);

    mega_kernel<<<NBLK, 256, SMEM_TOTAL>>>(
        spatial_obs, card_ctx, adj, ctx_W, ctx_b, lnc_s, lnc_b, in_W, in_b,
        lnp_s, lnp_b, cp_W, cp_b, Wl, Wr, Wa, op_W, op_b,
        card_W, card_b, at_W, at_b, src_W, src_b, tgt_W, tgt_b,
        v1_W, v1_b, v2_W, v2_b, out);
}

// round 15
// speedup vs baseline: 1.5652x; 1.5652x over previous
#include <cuda_runtime.h>
#include <cuda_bf16.h>
#include <math.h>
#include <stdint.h>

#define B 64
#define NP 32
#define NS 72
#define HD 256
#define H 4
#define F 64
#define CSE 112
#define L 4
#define NC 110
#define EPS 1e-6f

// ---------------- device scratch (no allocations; device-code refs only) ----------------
__device__ float g_c [L*B*HD];
__device__ float g_x [B*NS*HD];
__device__ float g_hl[B*NS*HD];
__device__ float g_hr[B*NS*HD];
__device__ __nv_bfloat16 g_Ghi[B*NS*HD];
__device__ __nv_bfloat16 g_Glo[B*NS*HD];
// weights K-major [n][k]; per layer 768 rows (Wl 256 | Wr 256 | op 256)
__device__ __nv_bfloat16 g_Bhi[L*768*HD];
__device__ __nv_bfloat16 g_Blo[L*768*HD];

#define SWZ128(bo) ((bo) ^ (((bo) >> 3) & 0x70))

__device__ __forceinline__ uint32_t smem_u32(const void* p) {
    uint32_t a;
    asm("{ .reg .u64 t; cvta.to.shared.u64 t, %1; cvt.u32.u64 %0, t; }" : "=r"(a) : "l"(p));
    return a;
}
#define LDM_X4(r0, r1, r2, r3, addr) \
    asm volatile("ldmatrix.sync.aligned.m8n8.x4.shared.b16 {%0,%1,%2,%3}, [%4];" \
                 : "=r"(r0), "=r"(r1), "=r"(r2), "=r"(r3) : "r"(addr))
#define CPA16(dst, src) \
    asm volatile("cp.async.cg.shared.global [%0], [%1], 16;" :: "r"(dst), "l"(src))
#define CPA_COMMIT() asm volatile("cp.async.commit_group;" ::: "memory")

__device__ __forceinline__ void mma_bf16(float* c, const uint32_t* a, const uint32_t* b) {
    asm volatile(
        "mma.sync.aligned.m16n8k16.row.col.f32.bf16.bf16.f32 "
        "{%0,%1,%2,%3}, {%4,%5,%6,%7}, {%8,%9}, {%0,%1,%2,%3};"
        : "+f"(c[0]), "+f"(c[1]), "+f"(c[2]), "+f"(c[3])
        : "r"(a[0]), "r"(a[1]), "r"(a[2]), "r"(a[3]), "r"(b[0]), "r"(b[1]));
}
__device__ __forceinline__ uint32_t bf2u(__nv_bfloat162 v) { return *(uint32_t*)&v; }

// ---------------- block LN statistics over 256 threads ----------------
__device__ __forceinline__ void block_stats256(float val, float& mean, float& rstd) {
    float s = val, sq = val * val;
    #pragma unroll
    for (int o = 16; o; o >>= 1) {
        s  += __shfl_xor_sync(0xffffffffu, s,  o);
        sq += __shfl_xor_sync(0xffffffffu, sq, o);
    }
    __shared__ float ss[8], sqq[8];
    int lane = threadIdx.x & 31, w = threadIdx.x >> 5;
    if (lane == 0) { ss[w] = s; sqq[w] = sq; }
    __syncthreads();
    if (w == 0) {
        s  = (lane < 8) ? ss[lane]  : 0.f;
        sq = (lane < 8) ? sqq[lane] : 0.f;
        #pragma unroll
        for (int o = 4; o; o >>= 1) {
            s  += __shfl_xor_sync(0xffffffffu, s,  o);
            sq += __shfl_xor_sync(0xffffffffu, sq, o);
        }
        if (lane == 0) { ss[0] = s; sqq[0] = sq; }
    }
    __syncthreads();
    s = ss[0]; sq = sqq[0];
    mean = s * (1.f / 256.f);
    float var = sq * (1.f / 256.f) - mean * mean;
    rstd = rsqrtf(var + EPS);
}

// ---------------- fused prep: embed | convW | ctx+cp  (blockIdx dispatch) ----------------
__global__ void prep_kernel(
    const float* __restrict__ so, const float* __restrict__ in_W, const float* __restrict__ in_b,
    const float* __restrict__ cc, const float* __restrict__ ctx_W, const float* __restrict__ ctx_b,
    const float* __restrict__ lnc_s, const float* __restrict__ lnc_b,
    const float* __restrict__ cp_W, const float* __restrict__ cp_b,
    const float* __restrict__ Wl, const float* __restrict__ Wr, const float* __restrict__ Wo) {
    int bid = blockIdx.x, tid = threadIdx.x;
    __shared__ float sv[NP];
    __shared__ float t[32][33];
    __shared__ float cs[CSE];
    __shared__ float gs[HD];
    if (bid < B*NS) {
        int b = bid / NS, s = bid - b*NS;
        if (tid < NP) sv[tid] = so[(b*NP + tid)*NS + s];
        __syncthreads();
        float acc = in_b[tid];
        #pragma unroll
        for (int p = 0; p < NP; p++) acc += sv[p] * in_W[p*HD + tid];
        g_x[bid*HD + tid] = acc;
    } else if (bid < B*NS + 768) {
        int idx = bid - B*NS;
        int kt = idx & 7, nt = (idx >> 3) & 7, m = idx >> 6;
        int l = m / 3, sel = m - l*3;
        const float* src = (sel == 0 ? Wl : sel == 1 ? Wr : Wo) + (size_t)l*HD*HD;
        int k0 = kt*32, n0 = nt*32;
        int x = tid & 31, y = tid >> 5;
        #pragma unroll
        for (int yy = y; yy < 32; yy += 8)
            t[yy][x] = src[(size_t)(k0 + yy)*HD + n0 + x];
        __syncthreads();
        int drow0 = l*768 + sel*256 + n0;
        #pragma unroll
        for (int yy = y; yy < 32; yy += 8) {
            float v = t[x][yy];
            __nv_bfloat16 hh = __float2bfloat16(v);
            size_t di = (size_t)(drow0 + yy)*HD + k0 + x;
            g_Bhi[di] = hh;
            g_Blo[di] = __float2bfloat16(v - __bfloat162float(hh));
        }
    } else {
        int idx = bid - (B*NS + 768);
        int b = idx & 63, l = idx >> 6;
        if (tid < CSE) cs[tid] = cc[b*CSE + tid];
        __syncthreads();
        float acc = ctx_b[tid];
        #pragma unroll 4
        for (int k = 0; k < CSE; k++) acc += cs[k] * ctx_W[k*HD + tid];
        float mean, rstd;
        block_stats256(acc, mean, rstd);
        gs[tid] = fmaxf((acc - mean)*rstd*lnc_s[tid] + lnc_b[tid], 0.f);
        __syncthreads();
        const float* W = cp_W + (size_t)l*HD*HD;
        float a2 = cp_b[l*HD + tid];
        #pragma unroll 16
        for (int k = 0; k < HD; k++) a2 += gs[k] * W[k*HD + tid];
        g_c[(l*B + b)*HD + tid] = a2;
    }
}

// ---------------- gemm0 with fused LayerNorm prologue ----------------
#define G0_AH 0
#define G0_AL 16384
#define G0_BH 32768
#define G0_BL 40960
#define G0_ST 49152
#define G0_TOTAL (49152 + 128*2*4)
__global__ void __launch_bounds__(256) gemm0ln(int l, const float* __restrict__ lns,
                                               const float* __restrict__ lnb) {
    extern __shared__ char smc[];
    uint32_t sbase = smem_u32(smc);
    float* stats = (float*)(smc + G0_ST);
    int tid = threadIdx.x, lane = tid & 31, warp = tid >> 5;
    int wm = warp >> 1, wn = warp & 1;
    int m0 = blockIdx.x * 128, nloc = blockIdx.y * 64;
    const __nv_bfloat16* Bhi = g_Bhi + (size_t)(l*768 + nloc) * HD;
    const __nv_bfloat16* Blo = g_Blo + (size_t)(l*768 + nloc) * HD;

    int row = tid >> 1, half = tid & 1;
    {
        const float4* xr = (const float4*)(g_x + (size_t)(m0 + row)*HD + half*128);
        float s = 0.f, sq = 0.f;
        #pragma unroll
        for (int c = 0; c < 32; c++) {
            float4 v = xr[c];
            s  += v.x + v.y + v.z + v.w;
            sq += v.x*v.x + v.y*v.y + v.z*v.z + v.w*v.w;
        }
        s  += __shfl_xor_sync(0xffffffffu, s, 1);
        sq += __shfl_xor_sync(0xffffffffu, sq, 1);
        if (half == 0) {
            float mean = s * (1.f/256.f);
            float var  = sq * (1.f/256.f) - mean*mean;
            stats[row*2]     = mean;
            stats[row*2 + 1] = rsqrtf(var + EPS);
        }
    }
    __syncthreads();

    int bidx = (m0 + row) / NS;
    const float* crow = g_c + (size_t)(l*B + bidx)*HD;
    int brow = tid >> 2, bq = tid & 3;
    int sub = lane >> 3, lrow = lane & 7;
    int lr = lane >> 2, lc2 = (lane & 3) * 2;

    float acc[2][4][4];
    #pragma unroll
    for (int mt = 0; mt < 2; mt++)
        #pragma unroll
        for (int nt = 0; nt < 4; nt++)
            #pragma unroll
            for (int c = 0; c < 4; c++) acc[mt][nt][c] = 0.f;

    for (int kc = 0; kc < 4; kc++) {
        if (kc) __syncthreads();
        {
            float mean = stats[row*2], rstd = stats[row*2 + 1];
            int colbase = kc*64 + half*32;
            const float4* src = (const float4*)(g_x + (size_t)(m0 + row)*HD + colbase);
            const float4* ls4 = (const float4*)(lns + colbase);
            const float4* lb4 = (const float4*)(lnb + colbase);
            const float4* cr4 = (const float4*)(crow + colbase);
            #pragma unroll
            for (int c = 0; c < 8; c++) {
                float4 v = src[c], sg = ls4[c], bt = lb4[c], cv = cr4[c];
                float y0 = (v.x - mean)*rstd*sg.x + bt.x + cv.x;
                float y1 = (v.y - mean)*rstd*sg.y + bt.y + cv.y;
                float y2 = (v.z - mean)*rstd*sg.z + bt.z + cv.z;
                float y3 = (v.w - mean)*rstd*sg.w + bt.w + cv.w;
                __nv_bfloat162 h01 = __floats2bfloat162_rn(y0, y1);
                __nv_bfloat162 h23 = __floats2bfloat162_rn(y2, y3);
                __nv_bfloat162 l01 = __floats2bfloat162_rn(y0 - __bfloat162float(h01.x),
                                                           y1 - __bfloat162float(h01.y));
                __nv_bfloat162 l23 = __floats2bfloat162_rn(y2 - __bfloat162float(h23.x),
                                                           y3 - __bfloat162float(h23.y));
                uint32_t sw = SWZ128((uint32_t)(row*128 + half*64 + c*8));
                *(uint2*)(smc + G0_AH + sw) = make_uint2(bf2u(h01), bf2u(h23));
                *(uint2*)(smc + G0_AL + sw) = make_uint2(bf2u(l01), bf2u(l23));
            }
        }
        {
            const uint4* bh4 = (const uint4*)((const char*)(Bhi + (size_t)brow*HD + kc*64) + bq*32);
            const uint4* bl4 = (const uint4*)((const char*)(Blo + (size_t)brow*HD + kc*64) + bq*32);
            #pragma unroll
            for (int c = 0; c < 2; c++) {
                uint32_t sw = SWZ128((uint32_t)(brow*128 + bq*32 + c*16));
                *(uint4*)(smc + G0_BH + sw) = bh4[c];
                *(uint4*)(smc + G0_BL + sw) = bl4[c];
            }
        }
        __syncthreads();
        #pragma unroll
        for (int ks = 0; ks < 4; ks++) {
            uint32_t ah[2][4], al[2][4], bh[4][2], bl[4][2];
            #pragma unroll
            for (int mt = 0; mt < 2; mt++) {
                int ar = wm*32 + mt*16 + (sub & 1)*8 + lrow;
                int ac = ks*32 + (sub >> 1)*16;
                uint32_t off = SWZ128((uint32_t)(ar*128 + ac));
                LDM_X4(ah[mt][0], ah[mt][1], ah[mt][2], ah[mt][3], sbase + G0_AH + off);
                LDM_X4(al[mt][0], al[mt][1], al[mt][2], al[mt][3], sbase + G0_AL + off);
            }
            #pragma unroll
            for (int pair = 0; pair < 2; pair++) {
                int ntb = sub >> 1, khalf = sub & 1;
                int br = wn*32 + pair*16 + ntb*8 + lrow;
                int bc = ks*32 + khalf*16;
                uint32_t off = SWZ128((uint32_t)(br*128 + bc));
                LDM_X4(bh[2*pair][0], bh[2*pair][1], bh[2*pair+1][0], bh[2*pair+1][1],
                       sbase + G0_BH + off);
                LDM_X4(bl[2*pair][0], bl[2*pair][1], bl[2*pair+1][0], bl[2*pair+1][1],
                       sbase + G0_BL + off);
            }
            #pragma unroll
            for (int mt = 0; mt < 2; mt++)
                #pragma unroll
                for (int nt = 0; nt < 4; nt++) {
                    mma_bf16(acc[mt][nt], ah[mt], bh[nt]);
                    mma_bf16(acc[mt][nt], ah[mt], bl[nt]);
                    mma_bf16(acc[mt][nt], al[mt], bh[nt]);
                }
        }
    }

    #pragma unroll
    for (int mt = 0; mt < 2; mt++) {
        int r = m0 + wm*32 + mt*16 + lr;
        #pragma unroll
        for (int nt = 0; nt < 4; nt++) {
            int gn = nloc + wn*32 + nt*8 + lc2;
            float* C = (gn < 256) ? g_hl : g_hr;
            int cc2 = gn & 255;
            C[(size_t)r*HD + cc2]         = acc[mt][nt][0];
            C[(size_t)r*HD + cc2 + 1]     = acc[mt][nt][1];
            C[(size_t)(r+8)*HD + cc2]     = acc[mt][nt][2];
            C[(size_t)(r+8)*HD + cc2 + 1] = acc[mt][nt][3];
        }
    }
}

// ---------------- gemm1: g_x += (G @ opW^T) + bias ; cp.async double buffer ----------------
#define GSTAGE 49152
#define GSM_TOTAL (2*GSTAGE)
__global__ void __launch_bounds__(256) gemm1_mma(int wrow, const float* __restrict__ bias) {
    extern __shared__ char smc[];
    uint32_t sbase = smem_u32(smc);
    int tid = threadIdx.x, lane = tid & 31, warp = tid >> 5;
    int wm = warp >> 1, wn = warp & 1;
    int m0   = blockIdx.x * 128;
    int nloc = blockIdx.y * 64;
    const __nv_bfloat16* Bhi = g_Bhi + (size_t)(wrow + nloc) * HD;
    const __nv_bfloat16* Blo = g_Blo + (size_t)(wrow + nloc) * HD;
    int lr = lane >> 2, lc2 = (lane & 3) * 2;
    int arow = tid >> 1, ahalf = tid & 1;
    int brow = tid >> 2, bq = tid & 3;

    auto load_stage = [&](int kc, int buf) {
        uint32_t sb = sbase + buf * GSTAGE;
        const char* gAh = (const char*)(g_Ghi + (size_t)(m0 + arow)*HD + kc*64) + ahalf*64;
        const char* gAl = (const char*)(g_Glo + (size_t)(m0 + arow)*HD + kc*64) + ahalf*64;
        #pragma unroll
        for (int c = 0; c < 4; c++) {
            uint32_t sw = SWZ128((uint32_t)(arow*128 + ahalf*64 + c*16));
            CPA16(sb + sw, gAh + c*16);
            CPA16(sb + 16384 + sw, gAl + c*16);
        }
        const char* gBh = (const char*)(Bhi + (size_t)brow*HD + kc*64) + bq*32;
        const char* gBl = (const char*)(Blo + (size_t)brow*HD + kc*64) + bq*32;
        #pragma unroll
        for (int c = 0; c < 2; c++) {
            uint32_t sw = SWZ128((uint32_t)(brow*128 + bq*32 + c*16));
            CPA16(sb + 32768 + sw, gBh + c*16);
            CPA16(sb + 40960 + sw, gBl + c*16);
        }
        CPA_COMMIT();
    };

    float acc[2][4][4];
    #pragma unroll
    for (int mt = 0; mt < 2; mt++)
        #pragma unroll
        for (int nt = 0; nt < 4; nt++)
            #pragma unroll
            for (int c = 0; c < 4; c++) acc[mt][nt][c] = 0.f;

    load_stage(0, 0);
    load_stage(1, 1);
    int sub = lane >> 3, lrow = lane & 7;

    for (int kc = 0; kc < 4; kc++) {
        if (kc == 3) asm volatile("cp.async.wait_group 0;" ::: "memory");
        else         asm volatile("cp.async.wait_group 1;" ::: "memory");
        __syncthreads();
        uint32_t sb = sbase + (kc & 1) * GSTAGE;
        #pragma unroll
        for (int ks = 0; ks < 4; ks++) {
            uint32_t ah[2][4], al[2][4], bh[4][2], bl[4][2];
            #pragma unroll
            for (int mt = 0; mt < 2; mt++) {
                int ar = wm*32 + mt*16 + (sub & 1)*8 + lrow;
                int ac = ks*32 + (sub >> 1)*16;
                uint32_t off = SWZ128((uint32_t)(ar*128 + ac));
                LDM_X4(ah[mt][0], ah[mt][1], ah[mt][2], ah[mt][3], sb + off);
                LDM_X4(al[mt][0], al[mt][1], al[mt][2], al[mt][3], sb + 16384 + off);
            }
            #pragma unroll
            for (int pair = 0; pair < 2; pair++) {
                int ntb = sub >> 1, khalf = sub & 1;
                int br = wn*32 + pair*16 + ntb*8 + lrow;
                int bc = ks*32 + khalf*16;
                uint32_t off = SWZ128((uint32_t)(br*128 + bc));
                LDM_X4(bh[2*pair][0], bh[2*pair][1], bh[2*pair+1][0], bh[2*pair+1][1],
                       sb + 32768 + off);
                LDM_X4(bl[2*pair][0], bl[2*pair][1], bl[2*pair+1][0], bl[2*pair+1][1],
                       sb + 40960 + off);
            }
            #pragma unroll
            for (int mt = 0; mt < 2; mt++)
                #pragma unroll
                for (int nt = 0; nt < 4; nt++) {
                    mma_bf16(acc[mt][nt], ah[mt], bh[nt]);
                    mma_bf16(acc[mt][nt], ah[mt], bl[nt]);
                    mma_bf16(acc[mt][nt], al[mt], bh[nt]);
                }
        }
        __syncthreads();
        if (kc < 2) load_stage(kc + 2, kc & 1);
    }

    #pragma unroll
    for (int mt = 0; mt < 2; mt++) {
        int r = m0 + wm*32 + mt*16 + lr;
        #pragma unroll
        for (int nt = 0; nt < 4; nt++) {
            int gn = nloc + wn*32 + nt*8 + lc2;
            g_x[(size_t)r*HD + gn]         += acc[mt][nt][0] + bias[gn];
            g_x[(size_t)r*HD + gn + 1]     += acc[mt][nt][1] + bias[gn + 1];
            g_x[(size_t)(r+8)*HD + gn]     += acc[mt][nt][2] + bias[gn];
            g_x[(size_t)(r+8)*HD + gn + 1] += acc[mt][nt][3] + bias[gn + 1];
        }
    }
}

// ---------------- GATv2 attention: per-head tiles, conflict-free smem ----------------
// grid (B, H, NS/TIH). Tile = (batch b, head h, 36 target rows).
// hrT[f][73]: transposed hr head-slice, pad 73 (gcd(73,32)=1 -> conflict-free both passes).
#define TIH 36
#define A_HRT 0
#define A_HL  (64*73)
#define A_SC  (A_HL + TIH*64)
#define A_ADJ (A_SC + TIH*NS)
#define A_WA  (A_ADJ + TIH*NS)
#define ATTN_SMEM ((64*73 + TIH*64 + 2*TIH*NS + 64) * sizeof(float))
__global__ void __launch_bounds__(256) attn_kernel(const float* __restrict__ adj,
                                                   const float* __restrict__ Wa) {
    int b = blockIdx.x, h = blockIdx.y, i0 = blockIdx.z * TIH;
    int tid = threadIdx.x, lane = tid & 31, warp = tid >> 5;
    extern __shared__ float smf[];
    float* hrT  = smf + A_HRT;
    float* hl   = smf + A_HL;
    float* sc   = smf + A_SC;
    float* adjr = smf + A_ADJ;
    float* wa   = smf + A_WA;
    if (tid < 64) wa[tid] = Wa[h*F + tid];
    {
        int f = tid & 63, g = tid >> 6;
        for (int j = g; j < NS; j += 4)
            hrT[f*73 + j] = g_hr[(size_t)(b*NS + j)*HD + h*F + f];
        for (int i = g; i < TIH; i += 4)
            hl[i*64 + f] = g_hl[(size_t)(b*NS + i0 + i)*HD + h*F + f];
    }
    for (int k = tid; k < TIH*NS; k += 256)
        adjr[k] = adj[(i0 + k/NS)*NS + (k % NS)];
    __syncthreads();

    // scores: thread per (i,j); hl broadcast, hrT consecutive-j -> conflict-free
    for (int e = tid; e < TIH*NS; e += 256) {
        int i = e / NS, j = e - i*NS;
        float outv = -1e9f;
        if (adjr[e] > 0.f) {
            const float* pl = hl + i*64;
            float p = 0.f;
            #pragma unroll 16
            for (int f = 0; f < F; f++) {
                float v = pl[f] + hrT[f*73 + j];
                v = (v > 0.f) ? v : 0.2f * v;
                p = fmaf(wa[f], v, p);
            }
            outv = p;
        }
        sc[e] = outv;
    }
    __syncthreads();

    // softmax over j, warp per row
    for (int i = warp; i < TIH; i += 8) {
        float m = -1e30f;
        for (int j = lane; j < NS; j += 32) m = fmaxf(m, sc[i*NS + j]);
        #pragma unroll
        for (int o = 16; o; o >>= 1) m = fmaxf(m, __shfl_xor_sync(0xffffffffu, m, o));
        float s = 0.f;
        for (int j = lane; j < NS; j += 32) {
            float e2 = expf(sc[i*NS + j] - m);
            sc[i*NS + j] = e2; s += e2;
        }
        #pragma unroll
        for (int o = 16; o; o >>= 1) s += __shfl_xor_sync(0xffffffffu, s, o);
        float inv = 1.f / s;
        for (int j = lane; j < NS; j += 32) sc[i*NS + j] *= inv;
    }
    __syncthreads();

    // output: thread (f, i-group of 9); j-outer, hrT stride-73 conflict-free, sc broadcast
    int f = tid & 63, ig = tid >> 6;
    float acc[9] = {};
    for (int j = 0; j < NS; j++) {
        float hv = hrT[f*73 + j];
        #pragma unroll
        for (int ib = 0; ib < 9; ib++)
            acc[ib] = fmaf(sc[(ig*9 + ib)*NS + j], hv, acc[ib]);
    }
    #pragma unroll
    for (int ib = 0; ib < 9; ib++) {
        float v = acc[ib];
        __nv_bfloat16 hh = __float2bfloat16(v);
        size_t idx = (size_t)(b*NS + i0 + ig*9 + ib)*HD + h*F + f;
        g_Ghi[idx] = hh;
        g_Glo[idx] = __float2bfloat16(v - __bfloat162float(hh));
    }
}

// ---------------- output heads (mean fused) ----------------
#define OUT_CARD 0
#define OUT_AT   (B*NC)
#define OUT_SRC  (OUT_AT + B*3)
#define OUT_TGT  (OUT_SRC + B*NS)
#define OUT_VAL  (OUT_TGT + B*NS)
__global__ void heads_kernel(const float* __restrict__ cW, const float* __restrict__ cb,
                             const float* __restrict__ aW, const float* __restrict__ ab,
                             const float* __restrict__ sW, const float* __restrict__ sb,
                             const float* __restrict__ tW, const float* __restrict__ tb,
                             const float* __restrict__ v1W, const float* __restrict__ v1b,
                             const float* __restrict__ v2W, const float* __restrict__ v2b,
                             float* __restrict__ out) {
    int b = blockIdx.x, tid = threadIdx.x;
    __shared__ float ge[HD];
    __shared__ float vh[128];
    __shared__ float vpart[4];
    {
        float m = 0.f;
        #pragma unroll 8
        for (int s = 0; s < NS; s++) m += g_x[(size_t)(b*NS + s)*HD + tid];
        ge[tid] = m * (1.f / (float)NS);
    }
    __syncthreads();
    if (tid < NC) {
        float a = cb[tid];
        for (int k = 0; k < HD; k++) a += ge[k] * cW[k*NC + tid];
        out[OUT_CARD + b*NC + tid] = a;
    }
    if (tid < 3) {
        float a = ab[tid];
        for (int k = 0; k < HD; k++) a += ge[k] * aW[k*3 + tid];
        out[OUT_AT + b*3 + tid] = a;
    }
    if (tid < NS) {
        float a = sb[tid], t = tb[tid];
        for (int k = 0; k < HD; k++) { a += ge[k] * sW[k*NS + tid]; t += ge[k] * tW[k*NS + tid]; }
        out[OUT_SRC + b*NS + tid] = a;
        out[OUT_TGT + b*NS + tid] = t;
    }
    if (tid < 128) {
        float a = v1b[tid];
        for (int k = 0; k < HD; k++) a += ge[k] * v1W[k*128 + tid];
        vh[tid] = fmaxf(a, 0.f);
    }
    __syncthreads();
    if (tid < 128) {
        float p = vh[tid] * v2W[tid];
        #pragma unroll
        for (int o = 16; o; o >>= 1) p += __shfl_xor_sync(0xffffffffu, p, o);
        if ((tid & 31) == 0) vpart[tid >> 5] = p;
    }
    __syncthreads();
    if (tid == 0) {
        float s = vpart[0] + vpart[1] + vpart[2] + vpart[3] + v2b[0];
        out[OUT_VAL + b] = tanhf(s);
    }
}

// ---------------- launch ----------------
extern "C" void kernel_launch(void* const* d_in, const int* in_sizes, int n_in,
                              void* d_out, int out_size) {
    const float* spatial_obs = (const float*)d_in[0];
    const float* card_ctx    = (const float*)d_in[1];
    const float* adj         = (const float*)d_in[2];
    const float* ctx_W  = (const float*)d_in[3];
    const float* ctx_b  = (const float*)d_in[4];
    const float* lnc_s  = (const float*)d_in[5];
    const float* lnc_b  = (const float*)d_in[6];
    const float* in_W   = (const float*)d_in[7];
    const float* in_b   = (const float*)d_in[8];
    const float* lnp_s  = (const float*)d_in[9];
    const float* lnp_b  = (const float*)d_in[10];
    const float* cp_W   = (const float*)d_in[11];
    const float* cp_b   = (const float*)d_in[12];
    const float* Wl     = (const float*)d_in[13];
    const float* Wr     = (const float*)d_in[14];
    const float* Wa     = (const float*)d_in[15];
    const float* op_W   = (const float*)d_in[16];
    const float* op_b   = (const float*)d_in[17];
    const float* card_W = (const float*)d_in[18];
    const float* card_b = (const float*)d_in[19];
    const float* at_W   = (const float*)d_in[20];
    const float* at_b   = (const float*)d_in[21];
    const float* src_W  = (const float*)d_in[22];
    const float* src_b  = (const float*)d_in[23];
    const float* tgt_W  = (const float*)d_in[24];
    const float* tgt_b  = (const float*)d_in[25];
    const float* v1_W   = (const float*)d_in[26];
    const float* v1_b   = (const float*)d_in[27];
    const float* v2_W   = (const float*)d_in[28];
    const float* v2_b   = (const float*)d_in[29];
    float* out = (float*)d_out;

    cudaFuncSetAttribute(attn_kernel, cudaFuncAttributeMaxDynamicSharedMemorySize, ATTN_SMEM);
    cudaFuncSetAttribute(gemm0ln,     cudaFuncAttributeMaxDynamicSharedMemorySize, G0_TOTAL);
    cudaFuncSetAttribute(gemm1_mma,   cudaFuncAttributeMaxDynamicSharedMemorySize, GSM_TOTAL);

    prep_kernel<<<B*NS + 768 + 256, 256>>>(spatial_obs, in_W, in_b,
                                           card_ctx, ctx_W, ctx_b, lnc_s, lnc_b,
                                           cp_W, cp_b, Wl, Wr, op_W);

    dim3 g0(36, 8);
    dim3 g1(36, 4);
    dim3 agrid(B, H, NS/TIH);
    for (int l = 0; l < L; l++) {
        gemm0ln<<<g0, 256, G0_TOTAL>>>(l, lnp_s + l*HD, lnp_b + l*HD);
        attn_kernel<<<agrid, 256, ATTN_SMEM>>>(adj, Wa + l*H*F);
        gemm1_mma<<<g1, 256, GSM_TOTAL>>>(l*768 + 512, op_b + l*HD);
    }

    heads_kernel<<<B, 256>>>(card_W, card_b, at_W, at_b, src_W, src_b,
                             tgt_W, tgt_b, v1_W, v1_b, v2_W, v2_b, out);
}